// round 2
// baseline (speedup 1.0000x reference)
#include <cuda_runtime.h>

typedef unsigned long long u64;

#define TW 32
#define TH 32
#define HALO 5
#define RW (TW + 2*HALO)      // 42
#define RH (TH + 2*HALO)      // 42
#define NT 256
#define IMG 512
#define PLANE (IMG*IMG)

#define SSIM_C1 0.0001f
#define SSIM_C2 0.0009f

// Dynamic smem layout (bytes):
//   u64 raw[RH*RW]     : 42*42*8 = 14112   {x,y} interleaved
//   u64 mu [RH*TW]     : 42*32*8 = 10752   {hblur(x), hblur(y)}
//   u64 sq [RH*TW]     : 42*32*8 = 10752   {hblur(xx), hblur(yy)}
//   f32 xy [RH*TW]     : 42*32*4 =  5376   hblur(xy)
#define RAW_N (RH*RW)
#define HB_N  (RH*TW)
#define SMEM_BYTES (RAW_N*8 + HB_N*8 + HB_N*8 + HB_N*4)   // 40992

__device__ __forceinline__ u64 pack2(float a, float b) {
    u64 r; asm("mov.b64 %0,{%1,%2};" : "=l"(r) : "f"(a), "f"(b)); return r;
}
__device__ __forceinline__ void unpack2(u64 v, float& a, float& b) {
    asm("mov.b64 {%0,%1},%2;" : "=f"(a), "=f"(b) : "l"(v));
}
__device__ __forceinline__ u64 fma2(u64 a, u64 b, u64 c) {
    u64 r; asm("fma.rn.f32x2 %0,%1,%2,%3;" : "=l"(r) : "l"(a), "l"(b), "l"(c)); return r;
}
__device__ __forceinline__ u64 mul2(u64 a, u64 b) {
    u64 r; asm("mul.rn.f32x2 %0,%1,%2;" : "=l"(r) : "l"(a), "l"(b)); return r;
}

// 11-tap gaussian, sigma=1.5, normalized; symmetric -> 6 unique values
__device__ __forceinline__ constexpr float wk(int k) {
    constexpr float W6[6] = { 0.00102838f, 0.00759876f, 0.03600077f,
                              0.10936078f, 0.21300553f, 0.26601171f };
    return W6[k < 6 ? k : 10 - k];
}

__global__ void __launch_bounds__(NT, 4)
ssim_kernel(const float* __restrict__ x, const float* __restrict__ y,
            float* __restrict__ out)
{
    extern __shared__ char smem[];
    u64*   raw   = (u64*)smem;
    u64*   mu_pl = (u64*)(smem + RAW_N*8);
    u64*   sq_pl = (u64*)(smem + RAW_N*8 + HB_N*8);
    float* xy_pl = (float*)(smem + RAW_N*8 + 2*HB_N*8);

    const int tid   = threadIdx.x;
    const int bx    = blockIdx.x;           // 0..15
    const int by    = blockIdx.y;           // 0..15
    const int plane = blockIdx.z;           // 0..47

    const float* __restrict__ xp = x + (size_t)plane * PLANE;
    const float* __restrict__ yp = y + (size_t)plane * PLANE;

    const int gx0 = bx * TW - HALO;
    const int gy0 = by * TH - HALO;

    // ---------------- Stage 1: gmem -> smem raw tile ----------------------
    const bool interior = (gx0 >= 0) & (gy0 >= 0) &
                          (gx0 + RW <= IMG) & (gy0 + RH <= IMG);
    if (interior) {
        #pragma unroll 4
        for (int i = tid; i < RAW_N; i += NT) {
            int r = i / RW;
            int c = i - r * RW;
            int off = (gy0 + r) * IMG + (gx0 + c);
            raw[i] = pack2(__ldg(xp + off), __ldg(yp + off));
        }
    } else {
        #pragma unroll 4
        for (int i = tid; i < RAW_N; i += NT) {
            int r = i / RW;
            int c = i - r * RW;
            int gr = gy0 + r, gc = gx0 + c;
            float xv = 0.f, yv = 0.f;
            if ((unsigned)gr < (unsigned)IMG && (unsigned)gc < (unsigned)IMG) {
                int off = gr * IMG + gc;
                xv = __ldg(xp + off);
                yv = __ldg(yp + off);
            }
            raw[i] = pack2(xv, yv);
        }
    }
    __syncthreads();

    // ---------------- Stage 2: horizontal 11-tap, 4-col register block ----
    {
        u64 Wp[6];
        #pragma unroll
        for (int k = 0; k < 6; ++k) Wp[k] = pack2(wk(k), wk(k));

        for (int t = tid; t < RH * (TW/4); t += NT) {
            int row = t >> 3;
            int g   = (t & 7) * 4;
            const u64* rp = raw + row * RW + g;

            u64   amu[4], asq[4];
            float axy[4];
            #pragma unroll
            for (int i2 = 0; i2 < 4; ++i2) { amu[i2]=0; asq[i2]=0; axy[i2]=0.f; }

            #pragma unroll
            for (int p = 0; p < 14; ++p) {
                u64 v = rp[p];
                float vx, vy; unpack2(v, vx, vy);
                u64   s  = mul2(v, v);     // {xx, yy}
                float xyv = vx * vy;
                #pragma unroll
                for (int i2 = 0; i2 < 4; ++i2) {
                    int k = p - i2;
                    if (k >= 0 && k <= 10) {
                        u64 w = Wp[k < 6 ? k : 10 - k];
                        amu[i2] = fma2(v, w, amu[i2]);
                        asq[i2] = fma2(s, w, asq[i2]);
                        axy[i2] = fmaf(xyv, wk(k), axy[i2]);
                    }
                }
            }

            int o = row * TW + g;
            #pragma unroll
            for (int i2 = 0; i2 < 4; ++i2) {
                mu_pl[o + i2] = amu[i2];
                sq_pl[o + i2] = asq[i2];
                xy_pl[o + i2] = axy[i2];
            }
        }
    }
    __syncthreads();

    // ---------------- Stage 3: vertical 11-tap, 4-row register block ------
    {
        u64 Wp[6];
        #pragma unroll
        for (int k = 0; k < 6; ++k) Wp[k] = pack2(wk(k), wk(k));

        const int col = tid & 31;
        const int r0  = (tid >> 5) * 4;     // 8 segments x 4 rows = 32

        u64   bmu[4], bsq[4];
        float bxy[4];
        #pragma unroll
        for (int i2 = 0; i2 < 4; ++i2) { bmu[i2]=0; bsq[i2]=0; bxy[i2]=0.f; }

        #pragma unroll
        for (int p = 0; p < 14; ++p) {
            int idx = (r0 + p) * TW + col;
            u64   hm = mu_pl[idx];
            u64   hs = sq_pl[idx];
            float hx = xy_pl[idx];
            #pragma unroll
            for (int i2 = 0; i2 < 4; ++i2) {
                int k = p - i2;
                if (k >= 0 && k <= 10) {
                    u64 w = Wp[k < 6 ? k : 10 - k];
                    bmu[i2] = fma2(hm, w, bmu[i2]);
                    bsq[i2] = fma2(hs, w, bsq[i2]);
                    bxy[i2] = fmaf(hx, wk(k), bxy[i2]);
                }
            }
        }

        float* op = out + (size_t)plane * PLANE
                        + (size_t)(by * TH + r0) * IMG
                        + bx * TW + col;

        #pragma unroll
        for (int i2 = 0; i2 < 4; ++i2) {
            float mu1, mu2, exx, eyy;
            unpack2(bmu[i2], mu1, mu2);
            unpack2(bsq[i2], exx, eyy);
            float mu1mu2 = mu1 * mu2;
            float mu1sq  = mu1 * mu1;
            float mu2sq  = mu2 * mu2;
            float s11    = exx - mu1sq;
            float s22    = eyy - mu2sq;
            float s12    = bxy[i2] - mu1mu2;
            float num = fmaf(2.f, mu1mu2, SSIM_C1) * fmaf(2.f, s12, SSIM_C2);
            float den = (mu1sq + mu2sq + SSIM_C1) * (s11 + s22 + SSIM_C2);
            op[(size_t)i2 * IMG] = __fdividef(num, den);
        }
    }
}

extern "C" void kernel_launch(void* const* d_in, const int* in_sizes, int n_in,
                              void* d_out, int out_size)
{
    const float* x = (const float*)d_in[0];   // img_out  [16,3,512,512] f32
    const float* y = (const float*)d_in[1];   // img_target
    float* out = (float*)d_out;

    int planes = in_sizes[0] / PLANE;         // 48

    cudaFuncSetAttribute(ssim_kernel,
                         cudaFuncAttributeMaxDynamicSharedMemorySize,
                         SMEM_BYTES);

    dim3 grid(IMG / TW, IMG / TH, planes);    // (16, 16, 48)
    ssim_kernel<<<grid, NT, SMEM_BYTES>>>(x, y, out);
}

// round 3
// speedup vs baseline: 1.0408x; 1.0408x over previous
#include <cuda_runtime.h>

#define TW 32
#define TH 64
#define HALO 5
#define RW (TW + 2*HALO)      // 42
#define RH (TH + 2*HALO)      // 74
#define NT 256
#define IMG 512
#define PLANE (IMG*IMG)

#define SSIM_C1 0.0001f
#define SSIM_C2 0.0009f

// Dynamic smem (hb planes only):
//   float2 mu2 [RH*TW]  {mu1,mu2}   : 74*32*8 = 18944
//   float2 sq2 [RH*TW]  {Exx,Eyy}   : 18944
//   float  xy  [RH*TW]              :  9472
#define HB_N (RH*TW)
#define SMEM_BYTES (HB_N*8 + HB_N*8 + HB_N*4)   // 47360 -> 4 CTAs/SM

// 11-tap gaussian, sigma=1.5, normalized; symmetric
__device__ __forceinline__ constexpr float wk(int k) {
    constexpr float W6[6] = { 0.00102838f, 0.00759876f, 0.03600077f,
                              0.10936078f, 0.21300553f, 0.26601171f };
    return W6[k < 6 ? k : 10 - k];
}

__global__ void __launch_bounds__(NT, 4)
ssim_kernel(const float* __restrict__ x, const float* __restrict__ y,
            float* __restrict__ out)
{
    extern __shared__ char smem[];
    float2* mu_pl = (float2*)smem;
    float2* sq_pl = (float2*)(smem + HB_N*8);
    float*  xy_pl = (float*)(smem + 2*HB_N*8);

    const int tid   = threadIdx.x;
    const int bx    = blockIdx.x;           // 0..15
    const int by    = blockIdx.y;           // 0..7
    const int plane = blockIdx.z;           // 0..47

    const float* __restrict__ xp = x + (size_t)plane * PLANE;
    const float* __restrict__ yp = y + (size_t)plane * PLANE;

    const int gx0 = bx * TW - HALO;
    const int gy0 = by * TH - HALO;

    // ------- Stage H: fused gmem load + horizontal 11-tap, 4-col blocks ---
    const bool interior = (gx0 >= 0) & (gy0 >= 0) &
                          (gx0 + RW <= IMG) & (gy0 + RH <= IMG);

    for (int t = tid; t < RH * (TW/4); t += NT) {
        const int row = t >> 3;
        const int g   = (t & 7) * 4;

        float amu1[4] = {0,0,0,0}, amu2[4] = {0,0,0,0};
        float axx [4] = {0,0,0,0}, ayy [4] = {0,0,0,0}, axy[4] = {0,0,0,0};

        const int gr = gy0 + row;
        const int gc0 = gx0 + g;

        if (interior) {
            const float* xr = xp + gr * IMG + gc0;
            const float* yr = yp + gr * IMG + gc0;
            #pragma unroll
            for (int p = 0; p < 14; ++p) {
                float xv = __ldg(xr + p);
                float yv = __ldg(yr + p);
                float xxv = xv * xv;
                float yyv = yv * yv;
                float xyv = xv * yv;
                #pragma unroll
                for (int i2 = 0; i2 < 4; ++i2) {
                    int k = p - i2;
                    if (k >= 0 && k <= 10) {
                        amu1[i2] = fmaf(xv,  wk(k), amu1[i2]);
                        amu2[i2] = fmaf(yv,  wk(k), amu2[i2]);
                        axx [i2] = fmaf(xxv, wk(k), axx [i2]);
                        ayy [i2] = fmaf(yyv, wk(k), ayy [i2]);
                        axy [i2] = fmaf(xyv, wk(k), axy [i2]);
                    }
                }
            }
        } else {
            const bool rok = (unsigned)gr < (unsigned)IMG;
            const float* xr = xp + (rok ? gr : 0) * IMG;
            const float* yr = yp + (rok ? gr : 0) * IMG;
            #pragma unroll
            for (int p = 0; p < 14; ++p) {
                int gc = gc0 + p;
                bool ok = rok & ((unsigned)gc < (unsigned)IMG);
                int  c  = ok ? gc : 0;
                float xv = ok ? __ldg(xr + c) : 0.f;
                float yv = ok ? __ldg(yr + c) : 0.f;
                float xxv = xv * xv;
                float yyv = yv * yv;
                float xyv = xv * yv;
                #pragma unroll
                for (int i2 = 0; i2 < 4; ++i2) {
                    int k = p - i2;
                    if (k >= 0 && k <= 10) {
                        amu1[i2] = fmaf(xv,  wk(k), amu1[i2]);
                        amu2[i2] = fmaf(yv,  wk(k), amu2[i2]);
                        axx [i2] = fmaf(xxv, wk(k), axx [i2]);
                        ayy [i2] = fmaf(yyv, wk(k), ayy [i2]);
                        axy [i2] = fmaf(xyv, wk(k), axy [i2]);
                    }
                }
            }
        }

        const int o = row * TW + g;
        #pragma unroll
        for (int i2 = 0; i2 < 4; ++i2) {
            mu_pl[o + i2] = make_float2(amu1[i2], amu2[i2]);
            sq_pl[o + i2] = make_float2(axx [i2], ayy [i2]);
            xy_pl[o + i2] = axy[i2];
        }
    }
    __syncthreads();

    // ------- Stage V: vertical 11-tap, 8-row register block ---------------
    {
        const int col = tid & 31;
        const int r0  = (tid >> 5) * 8;     // 8 segments of 8 rows

        float bmu1[8], bmu2[8], bxx[8], byy[8], bxy[8];
        #pragma unroll
        for (int i2 = 0; i2 < 8; ++i2) {
            bmu1[i2]=0.f; bmu2[i2]=0.f; bxx[i2]=0.f; byy[i2]=0.f; bxy[i2]=0.f;
        }

        #pragma unroll
        for (int p = 0; p < 18; ++p) {
            const int idx = (r0 + p) * TW + col;
            float2 hm = mu_pl[idx];
            float2 hs = sq_pl[idx];
            float  hx = xy_pl[idx];
            #pragma unroll
            for (int i2 = 0; i2 < 8; ++i2) {
                int k = p - i2;
                if (k >= 0 && k <= 10) {
                    bmu1[i2] = fmaf(hm.x, wk(k), bmu1[i2]);
                    bmu2[i2] = fmaf(hm.y, wk(k), bmu2[i2]);
                    bxx [i2] = fmaf(hs.x, wk(k), bxx [i2]);
                    byy [i2] = fmaf(hs.y, wk(k), byy [i2]);
                    bxy [i2] = fmaf(hx,   wk(k), bxy [i2]);
                }
            }
        }

        float* op = out + (size_t)plane * PLANE
                        + (size_t)(by * TH + r0) * IMG
                        + bx * TW + col;

        #pragma unroll
        for (int i2 = 0; i2 < 8; ++i2) {
            float mu1    = bmu1[i2];
            float mu2    = bmu2[i2];
            float mu1mu2 = mu1 * mu2;
            float mu1sq  = mu1 * mu1;
            float mu2sq  = mu2 * mu2;
            float s11    = bxx[i2] - mu1sq;
            float s22    = byy[i2] - mu2sq;
            float s12    = bxy[i2] - mu1mu2;
            float num = fmaf(2.f, mu1mu2, SSIM_C1) * fmaf(2.f, s12, SSIM_C2);
            float den = (mu1sq + mu2sq + SSIM_C1) * (s11 + s22 + SSIM_C2);
            op[(size_t)i2 * IMG] = __fdividef(num, den);
        }
    }
}

extern "C" void kernel_launch(void* const* d_in, const int* in_sizes, int n_in,
                              void* d_out, int out_size)
{
    const float* x = (const float*)d_in[0];   // img_out  [16,3,512,512] f32
    const float* y = (const float*)d_in[1];   // img_target
    float* out = (float*)d_out;

    int planes = in_sizes[0] / PLANE;         // 48

    cudaFuncSetAttribute(ssim_kernel,
                         cudaFuncAttributeMaxDynamicSharedMemorySize,
                         SMEM_BYTES);

    dim3 grid(IMG / TW, IMG / TH, planes);    // (16, 8, 48)
    ssim_kernel<<<grid, NT, SMEM_BYTES>>>(x, y, out);
}